// round 1
// baseline (speedup 1.0000x reference)
#include <cuda_runtime.h>
#include <math.h>

#define NCLS 19
#define MCOMP 5
#define KCOMP 95          // NCLS * MCOMP
#define AF 64
#define LOG2PI_F 1.8378770664093453f
#define HF 256
#define WF 256

typedef unsigned long long u64;

// ---------------- device scratch (no allocs allowed) ----------------
__device__ float g_Q[KCOMP * AF];      // 1/var
__device__ float g_CK[KCOMP];          // A*log2pi + 2*sum(log sc)
__device__ float g_MT[NCLS * AF];      // l2-normalized memory means
__device__ float g_LDR[NCLS];          // log(class_target/class_sourse)
__device__ float g_blockCe[4096];
__device__ int   g_blockCnt[4096];

// ---------------- packed f32x2 helpers (Blackwell FFMA2 path) -------
__device__ __forceinline__ u64 pk2(float lo, float hi) {
    u64 r; asm("mov.b64 %0,{%1,%2};" : "=l"(r) : "f"(lo), "f"(hi)); return r;
}
__device__ __forceinline__ void upk2(u64 v, float& lo, float& hi) {
    asm("mov.b64 {%0,%1},%2;" : "=f"(lo), "=f"(hi) : "l"(v));
}
__device__ __forceinline__ u64 fma2_(u64 a, u64 b, u64 c) {
    u64 d; asm("fma.rn.f32x2 %0,%1,%2,%3;" : "=l"(d) : "l"(a), "l"(b), "l"(c)); return d;
}
__device__ __forceinline__ u64 mul2_(u64 a, u64 b) {
    u64 d; asm("mul.rn.f32x2 %0,%1,%2;" : "=l"(d) : "l"(a), "l"(b)); return d;
}

// ---------------- prep: tiny one-block precompute --------------------
__global__ void prep_kernel(const float* __restrict__ cov,
                            const float* __restrict__ tmem,
                            const float* __restrict__ ct,
                            const float* __restrict__ cs) {
    int tid = threadIdx.x;
    // inverse variances + log-det constants
    for (int k = tid; k < KCOMP; k += blockDim.x) {
        float acc = 0.f;
        for (int a = 0; a < AF; a++) {
            float s = cov[k * AF + a];
            g_Q[k * AF + a] = 1.0f / (s * s);
            acc += logf(s);
        }
        g_CK[k] = AF * LOG2PI_F + 2.f * acc;
    }
    // target_memory mean over axis 2 (100 samples)
    for (int idx = tid; idx < NCLS * AF; idx += blockDim.x) {
        const float* p = tmem + (size_t)idx * 100;
        float s = 0.f;
        for (int t = 0; t < 100; t++) s += p[t];
        g_MT[idx] = s * 0.01f;
    }
    __syncthreads();
    __shared__ float norms[NCLS];
    if (tid < NCLS) {
        float s = 0.f;
        for (int a = 0; a < AF; a++) { float v = g_MT[tid * AF + a]; s += v * v; }
        norms[tid] = fmaxf(sqrtf(s), 1e-12f);
        float r = ct[tid] / cs[tid];
        if (isnan(r)) r = 0.f;          // nan_to_num
        g_LDR[tid] = logf(r);
    }
    __syncthreads();
    for (int idx = tid; idx < NCLS * AF; idx += blockDim.x)
        g_MT[idx] = g_MT[idx] / norms[idx / AF];
}

// ---------------- main: one thread per feature pixel -----------------
__global__ __launch_bounds__(256) void main_kernel(
    const float* __restrict__ feat,
    const int*   __restrict__ mask,
    const float* __restrict__ mean) {
    extern __shared__ float smem[];
    float* sQ   = smem;                      // 6080
    float* sL   = sQ  + KCOMP * AF;          // 6080
    float* sMT  = sL  + KCOMP * AF;          // 1216
    float* sCK  = sMT + NCLS * AF;           // 96 (padded)
    float* sLDR = sCK + 96;                  // 20 (padded)
    float* sRed = sLDR + 20;                 // 256
    int*   sRedI = (int*)(sRed + 256);       // 256

    const int tid = threadIdx.x;

    // cooperative param load (vectorized, broadcast-read later)
    for (int i = tid; i < (KCOMP * AF) / 4; i += 256) {
        ((float4*)sQ)[i] = ((const float4*)g_Q)[i];
        ((float4*)sL)[i] = ((const float4*)mean)[i];   // loc reshape == mean layout
    }
    for (int i = tid; i < (NCLS * AF) / 4; i += 256)
        ((float4*)sMT)[i] = ((const float4*)g_MT)[i];
    if (tid < KCOMP) sCK[tid] = g_CK[tid];
    if (tid < NCLS)  sLDR[tid] = g_LDR[tid];
    __syncthreads();

    const int pix = blockIdx.x * 256 + tid;
    const int w = pix & (WF - 1);
    const int h = (pix >> 8) & (HF - 1);
    const int b = pix >> 16;

    // ---- load feature vector (coalesced across w), pack channel pairs, L2-normalize
    const float* fb = feat + ((size_t)b * AF * (HF * WF) + (size_t)h * WF + w);
    u64 x[AF / 2];
    u64 nacc = 0ull;
    #pragma unroll
    for (int j = 0; j < AF / 2; j++) {
        float lo = fb[(size_t)(2 * j)     * (HF * WF)];
        float hi = fb[(size_t)(2 * j + 1) * (HF * WF)];
        x[j] = pk2(lo, hi);
        nacc = fma2_(x[j], x[j], nacc);
    }
    float nlo, nhi; upk2(nacc, nlo, nhi);
    float inv = 1.f / fmaxf(sqrtf(nlo + nhi), 1e-12f);
    const u64 inv2 = pk2(inv, inv);
    #pragma unroll
    for (int j = 0; j < AF / 2; j++) x[j] = mul2_(x[j], inv2);

    // ---- validity from 4x4 mask block: valid <=> some non-ignore class count >= 12
    const int* mb = mask + ((size_t)b << 20) + (size_t)(h << 2) * 1024 + (w << 2);
    int lab[16];
    #pragma unroll
    for (int r = 0; r < 4; r++) {
        int4 v = *(const int4*)(mb + (size_t)r * 1024);
        lab[r * 4 + 0] = v.x; lab[r * 4 + 1] = v.y;
        lab[r * 4 + 2] = v.z; lab[r * 4 + 3] = v.w;
    }
    bool valid = false;
    #pragma unroll
    for (int i = 0; i < 16; i++) {
        int cnt = 0;
        #pragma unroll
        for (int j = 0; j < 16; j++) cnt += (lab[j] == lab[i]);
        if (lab[i] != 255 && cnt >= 12) valid = true;
    }

    // ---- fused pseudo-label + CE, all streaming (no per-class arrays)
    const u64 NEG1 = pk2(-1.f, -1.f);
    float bestL = -1e30f;
    float gm = -1e30f, Z = 0.f, glab = 0.f;   // streaming log-softmax over classes

    #pragma unroll 1
    for (int c = 0; c < NCLS; c++) {
        // sim logit: x . mean_target[c]
        const u64* mt = (const u64*)(sMT + c * AF);
        u64 sacc = 0ull;
        #pragma unroll
        for (int j = 0; j < AF / 2; j++) sacc = fma2_(x[j], mt[j], sacc);
        float slo, shi; upk2(sacc, slo, shi);
        const float simlog = slo + shi;

        float mmax = -1e30f, msum = 0.f, lmx = -1e30f;
        #pragma unroll
        for (int m = 0; m < MCOMP; m++) {
            const int k = c * MCOMP + m;
            const u64* q = (const u64*)(sQ + k * AF);
            const u64* l = (const u64*)(sL + k * AF);
            u64 macc = 0ull, dacc = 0ull;
            #pragma unroll
            for (int j = 0; j < AF / 2; j++) {
                u64 xv = x[j];
                u64 lv = l[j];
                u64 d  = fma2_(lv, NEG1, xv);   // x - loc
                u64 t  = mul2_(q[j], d);
                macc   = fma2_(t, d, macc);     // maha += q*(x-loc)^2
                dacc   = fma2_(xv, lv, dacc);   // x . loc
            }
            float alo, ahi; upk2(macc, alo, ahi);
            const float maha = alo + ahi;
            upk2(dacc, alo, ahi);
            const float dotl = alo + ahi;
            const float lp = -0.5f * (sCK[k] + maha);
            if (lp > mmax) { msum = msum * __expf(mmax - lp) + 1.f; mmax = lp; }
            else           { msum += __expf(lp - mmax); }
            lmx = fmaxf(lmx, dotl);
        }
        const float L = sLDR[c] + simlog + mmax + __logf(msum);
        const float g = lmx * 0.01f;            // logits_max = max_m (f.loc)/TEMP
        if (g > gm) { Z = Z * __expf(gm - g) + 1.f; gm = g; }
        else        { Z += __expf(g - gm); }
        if (L > bestL) { bestL = L; glab = g; } // first-max semantics (strict >)
    }

    const float ce = valid ? (gm + __logf(Z) - glab) : 0.f;
    const int   v  = valid ? 1 : 0;

    // deterministic in-block tree reduction
    sRed[tid] = ce; sRedI[tid] = v;
    __syncthreads();
    #pragma unroll
    for (int s = 128; s > 0; s >>= 1) {
        if (tid < s) { sRed[tid] += sRed[tid + s]; sRedI[tid] += sRedI[tid + s]; }
        __syncthreads();
    }
    if (tid == 0) {
        g_blockCe[blockIdx.x]  = sRed[0];
        g_blockCnt[blockIdx.x] = sRedI[0];
    }
}

// ---------------- finalize: deterministic partial reduction ----------
__global__ void finalize_kernel(float* __restrict__ out, int nblocks) {
    __shared__ float sf[256];
    __shared__ int   si[256];
    int tid = threadIdx.x;
    float s = 0.f; int c = 0;
    for (int i = tid; i < nblocks; i += 256) { s += g_blockCe[i]; c += g_blockCnt[i]; }
    sf[tid] = s; si[tid] = c;
    __syncthreads();
    #pragma unroll
    for (int st = 128; st > 0; st >>= 1) {
        if (tid < st) { sf[tid] += sf[tid + st]; si[tid] += si[tid + st]; }
        __syncthreads();
    }
    if (tid == 0) out[0] = sf[0] / fmaxf((float)si[0], 1.0f);
}

// ---------------- launch --------------------------------------------
extern "C" void kernel_launch(void* const* d_in, const int* in_sizes, int n_in,
                              void* d_out, int out_size) {
    const float* feat = (const float*)d_in[0];
    const int*   mask = (const int*)d_in[1];
    const float* mean = (const float*)d_in[2];
    const float* cov  = (const float*)d_in[3];
    const float* tmem = (const float*)d_in[4];
    const float* ct   = (const float*)d_in[5];
    const float* cs   = (const float*)d_in[6];

    const int B = in_sizes[0] / (AF * HF * WF);
    const int npix = B * HF * WF;
    const int nblocks = npix / 256;

    const size_t smem_bytes =
        (size_t)(KCOMP * AF * 2 + NCLS * AF + 96 + 20 + 256) * sizeof(float)
        + 256 * sizeof(int);

    cudaFuncSetAttribute(main_kernel,
                         cudaFuncAttributeMaxDynamicSharedMemorySize,
                         (int)smem_bytes);

    prep_kernel<<<1, 128>>>(cov, tmem, ct, cs);
    main_kernel<<<nblocks, 256, smem_bytes>>>(feat, mask, mean);
    finalize_kernel<<<1, 256>>>((float*)d_out, nblocks);
}